// round 1
// baseline (speedup 1.0000x reference)
#include <cuda_runtime.h>
#include <math.h>

// ---------------------------------------------------------------------------
// Problem constants (fixed shapes)
// ---------------------------------------------------------------------------
#define BWIN   64       // windows
#define NTOK   512      // tokens per window
#define CDIM   384      // channels
#define NHEAD  12
#define HDIM   32       // head dim
#define LPOS   3375     // (2*8-1)^3
#define PDIM   24       // pos mlp hidden
#define NGRP   8        // mask groups
#define SCALE  0.17677669529663687f   // 32^-0.5

// ---------------------------------------------------------------------------
// Scratch (device globals; no runtime allocation allowed)
// ---------------------------------------------------------------------------
__device__ float g_pos[LPOS * NHEAD];                       // (L, 12)
__device__ float g_bias[NHEAD * NTOK * NTOK];               // (12, 512, 512)
__device__ float g_Q[BWIN * NHEAD * NTOK * HDIM];           // (b,h,n,d) q*scale
__device__ float g_K[BWIN * NHEAD * NTOK * HDIM];
__device__ float g_V[BWIN * NHEAD * NTOK * HDIM];
__device__ float g_att[BWIN * NTOK * CDIM];                 // attention out (b,n,C)

// ---------------------------------------------------------------------------
// Kernel 1: dynamic position-bias MLP  (L rows, one thread each)
// ---------------------------------------------------------------------------
__device__ __forceinline__ void ln_relu(const float* in, float* t,
                                        const float* g, const float* bt) {
    float m = 0.f;
    #pragma unroll
    for (int i = 0; i < PDIM; i++) m += in[i];
    m *= (1.0f / PDIM);
    float v = 0.f;
    #pragma unroll
    for (int i = 0; i < PDIM; i++) { float d = in[i] - m; v += d * d; }
    v *= (1.0f / PDIM);
    float inv = rsqrtf(v + 1e-5f);
    #pragma unroll
    for (int i = 0; i < PDIM; i++) {
        float y = (in[i] - m) * inv * g[i] + bt[i];
        t[i] = fmaxf(y, 0.f);
    }
}

__global__ void pos_mlp_kernel(
    const float* __restrict__ pw,  const float* __restrict__ pb,
    const float* __restrict__ g1,  const float* __restrict__ b1,
    const float* __restrict__ w1,  const float* __restrict__ wb1,
    const float* __restrict__ g2,  const float* __restrict__ b2,
    const float* __restrict__ w2,  const float* __restrict__ wb2,
    const float* __restrict__ g3,  const float* __restrict__ b3,
    const float* __restrict__ w3,  const float* __restrict__ wb3)
{
    int l = blockIdx.x * blockDim.x + threadIdx.x;
    if (l >= LPOS) return;
    float c0 = (float)(l / 225 - 7);
    float c1 = (float)((l / 15) % 15 - 7);
    float c2 = (float)(l % 15 - 7);

    float v0[PDIM], v1[PDIM], v2[PDIM], t[PDIM];
    #pragma unroll
    for (int o = 0; o < PDIM; o++)
        v0[o] = c0 * pw[o] + c1 * pw[PDIM + o] + c2 * pw[2 * PDIM + o] + pb[o];

    ln_relu(v0, t, g1, b1);
    #pragma unroll
    for (int o = 0; o < PDIM; o++) {
        float s = wb1[o];
        #pragma unroll
        for (int i = 0; i < PDIM; i++) s = fmaf(t[i], w1[i * PDIM + o], s);
        v1[o] = s;
    }
    ln_relu(v1, t, g2, b2);
    #pragma unroll
    for (int o = 0; o < PDIM; o++) {
        float s = wb2[o];
        #pragma unroll
        for (int i = 0; i < PDIM; i++) s = fmaf(t[i], w2[i * PDIM + o], s);
        v2[o] = s;
    }
    ln_relu(v2, t, g3, b3);
    #pragma unroll
    for (int o = 0; o < NHEAD; o++) {
        float s = wb3[o];
        #pragma unroll
        for (int i = 0; i < PDIM; i++) s = fmaf(t[i], w3[i * NHEAD + o], s);
        g_pos[l * NHEAD + o] = s;
    }
}

// ---------------------------------------------------------------------------
// Kernel 2: expand bias table  bias[h][n][m] = pos[rpi(n,m)][h]
// ---------------------------------------------------------------------------
__global__ void bias_fill_kernel() {
    int t = blockIdx.x * blockDim.x + threadIdx.x;   // 512*512 threads
    int n = t >> 9, m = t & 511;
    int i1 = n >> 6, j1 = (n >> 3) & 7, k1 = n & 7;
    int i2 = m >> 6, j2 = (m >> 3) & 7, k2 = m & 7;
    int idx = ((i1 - i2 + 7) * 15 + (j1 - j2 + 7)) * 15 + (k1 - k2 + 7);
    #pragma unroll
    for (int h = 0; h < NHEAD; h++)
        g_bias[((size_t)h * NTOK + n) * NTOK + m] = g_pos[idx * NHEAD + h];
}

// ---------------------------------------------------------------------------
// Kernel 3/5: tiled fp32 GEMM  C = A(32768x384) @ B(384xN) + bias
//   mode 0: B=qkv_w (N=1152), scatter into g_Q/g_K/g_V (q scaled)
//   mode 1: A=g_att, B=proj_w (N=384), write d_out
// ---------------------------------------------------------------------------
__global__ __launch_bounds__(256)
void gemm_kernel(const float* __restrict__ A, const float* __restrict__ B,
                 const float* __restrict__ bias, int Ncols, int mode,
                 float* __restrict__ out)
{
    __shared__ float As[16][128];
    __shared__ float Bs[16][64];

    const float* Ap = (mode == 1) ? g_att : A;
    int m0 = blockIdx.y * 128;
    int n0 = blockIdx.x * 64;
    int tid = threadIdx.x;
    int ty = tid >> 4, tx = tid & 15;

    float acc[8][4];
    #pragma unroll
    for (int i = 0; i < 8; i++)
        #pragma unroll
        for (int j = 0; j < 4; j++) acc[i][j] = 0.f;

    for (int k0 = 0; k0 < CDIM; k0 += 16) {
        // load A tile (128x16) as float4 along k
        #pragma unroll
        for (int e = 0; e < 2; e++) {
            int c = tid + e * 256;
            int row = c >> 2, kq = c & 3;
            float4 v = *(const float4*)(Ap + (size_t)(m0 + row) * CDIM + k0 + kq * 4);
            As[kq * 4 + 0][row] = v.x;
            As[kq * 4 + 1][row] = v.y;
            As[kq * 4 + 2][row] = v.z;
            As[kq * 4 + 3][row] = v.w;
        }
        // load B tile (16x64)
        {
            int kk = tid >> 4, nq = tid & 15;
            float4 v = *(const float4*)(B + (size_t)(k0 + kk) * Ncols + n0 + nq * 4);
            *(float4*)&Bs[kk][nq * 4] = v;
        }
        __syncthreads();
        #pragma unroll
        for (int kk = 0; kk < 16; kk++) {
            float a[8], bf[4];
            *(float4*)&a[0] = *(float4*)&As[kk][ty * 8];
            *(float4*)&a[4] = *(float4*)&As[kk][ty * 8 + 4];
            *(float4*)&bf[0] = *(float4*)&Bs[kk][tx * 4];
            #pragma unroll
            for (int i = 0; i < 8; i++)
                #pragma unroll
                for (int j = 0; j < 4; j++)
                    acc[i][j] = fmaf(a[i], bf[j], acc[i][j]);
        }
        __syncthreads();
    }

    // epilogue
    #pragma unroll
    for (int i = 0; i < 8; i++) {
        int gm = m0 + ty * 8 + i;
        #pragma unroll
        for (int j = 0; j < 4; j++) {
            int gn = n0 + tx * 4 + j;
            float val = acc[i][j] + bias[gn];
            if (mode == 0) {
                int which = gn / CDIM;
                int r = gn - which * CDIM;
                int h = r >> 5, dd = r & 31;
                int b = gm >> 9, tok = gm & 511;
                size_t off = (((size_t)b * NHEAD + h) * NTOK + tok) * HDIM + dd;
                if (which == 0)      g_Q[off] = val * SCALE;
                else if (which == 1) g_K[off] = val;
                else                 g_V[off] = val;
            } else {
                out[(size_t)gm * CDIM + gn] = val;
            }
        }
    }
}

// ---------------------------------------------------------------------------
// Kernel 4: fused flash attention, fp32. One thread per query row.
// Grid (4 rowblocks, 12 heads, 64 windows), 128 threads.
// ---------------------------------------------------------------------------
__global__ __launch_bounds__(128)
void attn_kernel(const float* __restrict__ mask)
{
    __shared__ float Ks[64][32];
    __shared__ float Vs[64][32];

    int rb = blockIdx.x, h = blockIdx.y, b = blockIdx.z;
    int r = rb * 128 + threadIdx.x;

    const float* Qp    = g_Q + (((size_t)b * NHEAD + h) * NTOK + r) * HDIM;
    const float* Kbase = g_K + ((size_t)b * NHEAD + h) * NTOK * HDIM;
    const float* Vbase = g_V + ((size_t)b * NHEAD + h) * NTOK * HDIM;
    const float* biasrow = g_bias + ((size_t)h * NTOK + r) * NTOK;
    const float* maskrow = mask + ((size_t)(b & 7) * NTOK + r) * NTOK;

    float q[32], o[32];
    #pragma unroll
    for (int kk = 0; kk < 32; kk += 4) {
        float4 v = *(const float4*)(Qp + kk);
        q[kk] = v.x; q[kk + 1] = v.y; q[kk + 2] = v.z; q[kk + 3] = v.w;
        o[kk] = 0.f; o[kk + 1] = 0.f; o[kk + 2] = 0.f; o[kk + 3] = 0.f;
    }
    float mr = -1e30f, lr = 0.f;

    for (int ct = 0; ct < 8; ct++) {
        __syncthreads();
        #pragma unroll
        for (int e = 0; e < 4; e++) {
            int c = threadIdx.x + e * 128;    // 0..511
            int j = c >> 3, dq = (c & 7) * 4;
            *(float4*)&Ks[j][dq] = *(const float4*)(Kbase + (size_t)(ct * 64 + j) * HDIM + dq);
            *(float4*)&Vs[j][dq] = *(const float4*)(Vbase + (size_t)(ct * 64 + j) * HDIM + dq);
        }
        __syncthreads();

        float s[64];
        #pragma unroll 8
        for (int j = 0; j < 64; j++) {
            float s0 = 0.f, s1 = 0.f;
            #pragma unroll
            for (int kk = 0; kk < 32; kk += 8) {
                float4 k0v = *(float4*)&Ks[j][kk];
                float4 k1v = *(float4*)&Ks[j][kk + 4];
                s0 = fmaf(q[kk],     k0v.x, s0);
                s0 = fmaf(q[kk + 1], k0v.y, s0);
                s0 = fmaf(q[kk + 2], k0v.z, s0);
                s0 = fmaf(q[kk + 3], k0v.w, s0);
                s1 = fmaf(q[kk + 4], k1v.x, s1);
                s1 = fmaf(q[kk + 5], k1v.y, s1);
                s1 = fmaf(q[kk + 6], k1v.z, s1);
                s1 = fmaf(q[kk + 7], k1v.w, s1);
            }
            s[j] = s0 + s1;
        }
        // add bias + mask
        #pragma unroll
        for (int jq = 0; jq < 16; jq++) {
            float4 bb = *(const float4*)(biasrow + ct * 64 + jq * 4);
            float4 mm = *(const float4*)(maskrow + ct * 64 + jq * 4);
            s[jq * 4 + 0] += bb.x + mm.x;
            s[jq * 4 + 1] += bb.y + mm.y;
            s[jq * 4 + 2] += bb.z + mm.z;
            s[jq * 4 + 3] += bb.w + mm.w;
        }
        // online softmax
        float tmax = -1e30f;
        #pragma unroll
        for (int j = 0; j < 64; j++) tmax = fmaxf(tmax, s[j]);
        float nm = fmaxf(mr, tmax);
        float corr = __expf(mr - nm);
        float ls = 0.f;
        #pragma unroll
        for (int j = 0; j < 64; j++) { float p = __expf(s[j] - nm); s[j] = p; ls += p; }
        lr = lr * corr + ls;
        #pragma unroll
        for (int kk = 0; kk < 32; kk++) o[kk] *= corr;
        #pragma unroll 4
        for (int j = 0; j < 64; j++) {
            float p = s[j];
            #pragma unroll
            for (int kk = 0; kk < 32; kk += 4) {
                float4 v = *(float4*)&Vs[j][kk];
                o[kk]     = fmaf(p, v.x, o[kk]);
                o[kk + 1] = fmaf(p, v.y, o[kk + 1]);
                o[kk + 2] = fmaf(p, v.z, o[kk + 2]);
                o[kk + 3] = fmaf(p, v.w, o[kk + 3]);
            }
        }
        mr = nm;
    }

    float inv = 1.f / lr;
    float* op = g_att + ((size_t)b * NTOK + r) * CDIM + h * HDIM;
    #pragma unroll
    for (int kk = 0; kk < 32; kk += 4) {
        float4 v = make_float4(o[kk] * inv, o[kk + 1] * inv, o[kk + 2] * inv, o[kk + 3] * inv);
        *(float4*)(op + kk) = v;
    }
}

// ---------------------------------------------------------------------------
// Host launch
// ---------------------------------------------------------------------------
extern "C" void kernel_launch(void* const* d_in, const int* in_sizes, int n_in,
                              void* d_out, int out_size)
{
    const float *x = nullptr, *mask = nullptr, *qkv_w = nullptr, *qkv_b = nullptr;
    const float *proj_w = nullptr, *proj_b = nullptr;
    const float *pos_proj_w = nullptr, *pos_proj_b = nullptr;
    const float *ln1_g = nullptr, *ln1_b = nullptr, *pos1_w = nullptr, *pos1_b = nullptr;
    const float *ln2_g = nullptr, *ln2_b = nullptr, *pos2_w = nullptr, *pos2_b = nullptr;
    const float *ln3_g = nullptr, *ln3_b = nullptr, *pos3_w = nullptr, *pos3_b = nullptr;

    int cnt24 = 0, cnt576 = 0;
    for (int i = 0; i < n_in; i++) {
        int sz = in_sizes[i];
        const float* p = (const float*)d_in[i];
        switch (sz) {
            case 12582912: x = p; break;
            case 2097152:  mask = p; break;
            case 442368:   qkv_w = p; break;
            case 1152:     qkv_b = p; break;
            case 147456:   proj_w = p; break;
            case 384:      proj_b = p; break;
            case 72:       pos_proj_w = p; break;
            case 288:      pos3_w = p; break;
            case 12:       pos3_b = p; break;
            case 576:
                if (cnt576 == 0) pos1_w = p; else pos2_w = p;
                cnt576++;
                break;
            case 24: {
                // metadata order: pos_proj_b, ln1_g, ln1_b, pos1_b,
                //                 ln2_g, ln2_b, pos2_b, ln3_g, ln3_b
                switch (cnt24) {
                    case 0: pos_proj_b = p; break;
                    case 1: ln1_g = p; break;
                    case 2: ln1_b = p; break;
                    case 3: pos1_b = p; break;
                    case 4: ln2_g = p; break;
                    case 5: ln2_b = p; break;
                    case 6: pos2_b = p; break;
                    case 7: ln3_g = p; break;
                    case 8: ln3_b = p; break;
                }
                cnt24++;
                break;
            }
            default: break; // H, W, D scalars
        }
    }

    // 1. pos MLP table
    pos_mlp_kernel<<<(LPOS + 127) / 128, 128>>>(
        pos_proj_w, pos_proj_b,
        ln1_g, ln1_b, pos1_w, pos1_b,
        ln2_g, ln2_b, pos2_w, pos2_b,
        ln3_g, ln3_b, pos3_w, pos3_b);

    // 2. expand to per-head bias table
    bias_fill_kernel<<<(NTOK * NTOK) / 256, 256>>>();

    // 3. QKV GEMM + scatter
    gemm_kernel<<<dim3(1152 / 64, (BWIN * NTOK) / 128), 256>>>(
        x, qkv_w, qkv_b, 1152, 0, nullptr);

    // 4. fused attention
    attn_kernel<<<dim3(NTOK / 128, NHEAD, BWIN), 128>>>(mask);

    // 5. output projection
    gemm_kernel<<<dim3(CDIM / 64, (BWIN * NTOK) / 128), 256>>>(
        nullptr, proj_w, proj_b, CDIM, 1, (float*)d_out);

    (void)out_size;
}

// round 2
// speedup vs baseline: 1.2261x; 1.2261x over previous
#include <cuda_runtime.h>
#include <math.h>

// ---------------------------------------------------------------------------
// Problem constants (fixed shapes)
// ---------------------------------------------------------------------------
#define BWIN   64       // windows
#define NTOK   512      // tokens per window
#define CDIM   384      // channels
#define NHEAD  12
#define HDIM   32       // head dim
#define LPOS   3375     // (2*8-1)^3
#define PDIM   24       // pos mlp hidden
#define NGRP   8        // mask groups
#define SCALE  0.17677669529663687f   // 32^-0.5

// ---------------------------------------------------------------------------
// Scratch (device globals; no runtime allocation allowed)
// ---------------------------------------------------------------------------
__device__ float g_pos[LPOS * NHEAD];                       // (L, 12)
__device__ float g_bias[NHEAD * NTOK * NTOK];               // (12, 512, 512)
__device__ float g_Q[BWIN * NHEAD * NTOK * HDIM];           // (b,h,n,d) q*scale
__device__ float g_K[BWIN * NHEAD * NTOK * HDIM];
__device__ float g_V[BWIN * NHEAD * NTOK * HDIM];
__device__ float g_att[BWIN * NTOK * CDIM];                 // attention out (b,n,C)

// ---------------------------------------------------------------------------
// Kernel 1: dynamic position-bias MLP  (L rows, one thread each)
// ---------------------------------------------------------------------------
__device__ __forceinline__ void ln_relu(const float* in, float* t,
                                        const float* g, const float* bt) {
    float m = 0.f;
    #pragma unroll
    for (int i = 0; i < PDIM; i++) m += in[i];
    m *= (1.0f / PDIM);
    float v = 0.f;
    #pragma unroll
    for (int i = 0; i < PDIM; i++) { float d = in[i] - m; v += d * d; }
    v *= (1.0f / PDIM);
    float inv = rsqrtf(v + 1e-5f);
    #pragma unroll
    for (int i = 0; i < PDIM; i++) {
        float y = (in[i] - m) * inv * g[i] + bt[i];
        t[i] = fmaxf(y, 0.f);
    }
}

__global__ void pos_mlp_kernel(
    const float* __restrict__ pw,  const float* __restrict__ pb,
    const float* __restrict__ g1,  const float* __restrict__ b1,
    const float* __restrict__ w1,  const float* __restrict__ wb1,
    const float* __restrict__ g2,  const float* __restrict__ b2,
    const float* __restrict__ w2,  const float* __restrict__ wb2,
    const float* __restrict__ g3,  const float* __restrict__ b3,
    const float* __restrict__ w3,  const float* __restrict__ wb3)
{
    int l = blockIdx.x * blockDim.x + threadIdx.x;
    if (l >= LPOS) return;
    float c0 = (float)(l / 225 - 7);
    float c1 = (float)((l / 15) % 15 - 7);
    float c2 = (float)(l % 15 - 7);

    float v0[PDIM], v1[PDIM], v2[PDIM], t[PDIM];
    #pragma unroll
    for (int o = 0; o < PDIM; o++)
        v0[o] = c0 * pw[o] + c1 * pw[PDIM + o] + c2 * pw[2 * PDIM + o] + pb[o];

    ln_relu(v0, t, g1, b1);
    #pragma unroll
    for (int o = 0; o < PDIM; o++) {
        float s = wb1[o];
        #pragma unroll
        for (int i = 0; i < PDIM; i++) s = fmaf(t[i], w1[i * PDIM + o], s);
        v1[o] = s;
    }
    ln_relu(v1, t, g2, b2);
    #pragma unroll
    for (int o = 0; o < PDIM; o++) {
        float s = wb2[o];
        #pragma unroll
        for (int i = 0; i < PDIM; i++) s = fmaf(t[i], w2[i * PDIM + o], s);
        v2[o] = s;
    }
    ln_relu(v2, t, g3, b3);
    #pragma unroll
    for (int o = 0; o < NHEAD; o++) {
        float s = wb3[o];
        #pragma unroll
        for (int i = 0; i < PDIM; i++) s = fmaf(t[i], w3[i * NHEAD + o], s);
        g_pos[l * NHEAD + o] = s;
    }
}

// ---------------------------------------------------------------------------
// Kernel 2: expand bias table  bias[h][n][m] = pos[rpi(n,m)][h]
// ---------------------------------------------------------------------------
__global__ void bias_fill_kernel() {
    int t = blockIdx.x * blockDim.x + threadIdx.x;   // 512*512 threads
    int n = t >> 9, m = t & 511;
    int i1 = n >> 6, j1 = (n >> 3) & 7, k1 = n & 7;
    int i2 = m >> 6, j2 = (m >> 3) & 7, k2 = m & 7;
    int idx = ((i1 - i2 + 7) * 15 + (j1 - j2 + 7)) * 15 + (k1 - k2 + 7);
    #pragma unroll
    for (int h = 0; h < NHEAD; h++)
        g_bias[((size_t)h * NTOK + n) * NTOK + m] = g_pos[idx * NHEAD + h];
}

// ---------------------------------------------------------------------------
// Kernel 3/5: tiled fp32 GEMM  C = A(32768x384) @ B(384xN) + bias
//   mode 0: B=qkv_w (N=1152), scatter into g_Q/g_K/g_V (q scaled)
//   mode 1: A=g_att, B=proj_w (N=384), write d_out
// ---------------------------------------------------------------------------
__global__ __launch_bounds__(256)
void gemm_kernel(const float* __restrict__ A, const float* __restrict__ B,
                 const float* __restrict__ bias, int Ncols, int mode,
                 float* __restrict__ out)
{
    __shared__ float As[16][128];
    __shared__ float Bs[16][64];

    const float* Ap = (mode == 1) ? g_att : A;
    int m0 = blockIdx.y * 128;
    int n0 = blockIdx.x * 64;
    int tid = threadIdx.x;
    int ty = tid >> 4, tx = tid & 15;

    float acc[8][4];
    #pragma unroll
    for (int i = 0; i < 8; i++)
        #pragma unroll
        for (int j = 0; j < 4; j++) acc[i][j] = 0.f;

    for (int k0 = 0; k0 < CDIM; k0 += 16) {
        // load A tile (128x16) as float4 along k
        #pragma unroll
        for (int e = 0; e < 2; e++) {
            int c = tid + e * 256;
            int row = c >> 2, kq = c & 3;
            float4 v = *(const float4*)(Ap + (size_t)(m0 + row) * CDIM + k0 + kq * 4);
            As[kq * 4 + 0][row] = v.x;
            As[kq * 4 + 1][row] = v.y;
            As[kq * 4 + 2][row] = v.z;
            As[kq * 4 + 3][row] = v.w;
        }
        // load B tile (16x64)
        {
            int kk = tid >> 4, nq = tid & 15;
            float4 v = *(const float4*)(B + (size_t)(k0 + kk) * Ncols + n0 + nq * 4);
            *(float4*)&Bs[kk][nq * 4] = v;
        }
        __syncthreads();
        #pragma unroll
        for (int kk = 0; kk < 16; kk++) {
            float a[8], bf[4];
            *(float4*)&a[0] = *(float4*)&As[kk][ty * 8];
            *(float4*)&a[4] = *(float4*)&As[kk][ty * 8 + 4];
            *(float4*)&bf[0] = *(float4*)&Bs[kk][tx * 4];
            #pragma unroll
            for (int i = 0; i < 8; i++)
                #pragma unroll
                for (int j = 0; j < 4; j++)
                    acc[i][j] = fmaf(a[i], bf[j], acc[i][j]);
        }
        __syncthreads();
    }

    // epilogue
    #pragma unroll
    for (int i = 0; i < 8; i++) {
        int gm = m0 + ty * 8 + i;
        #pragma unroll
        for (int j = 0; j < 4; j++) {
            int gn = n0 + tx * 4 + j;
            float val = acc[i][j] + bias[gn];
            if (mode == 0) {
                int which = gn / CDIM;
                int r = gn - which * CDIM;
                int h = r >> 5, dd = r & 31;
                int b = gm >> 9, tok = gm & 511;
                size_t off = (((size_t)b * NHEAD + h) * NTOK + tok) * HDIM + dd;
                if (which == 0)      g_Q[off] = val * SCALE;
                else if (which == 1) g_K[off] = val;
                else                 g_V[off] = val;
            } else {
                out[(size_t)gm * CDIM + gn] = val;
            }
        }
    }
}

// ---------------------------------------------------------------------------
// Kernel 4: fused flash attention, fp32, register-blocked.
// CTA = 128 queries x (one b, h); 8 key-tiles of 64. 256 threads.
// Thread (ty=tid>>3, tx=tid&7): S tile rows ty*4..+3, cols tx*8..+7;
//                               O tile rows ty*4..+3, cols tx*4..+3.
// Same query rows for S and O -> softmax stats stay in registers.
// ---------------------------------------------------------------------------
__global__ __launch_bounds__(256, 2)
void attn_kernel(const float* __restrict__ mask)
{
    __shared__ float Qt[32][128];   // [k][row], transposed Q tile
    __shared__ float Kt[32][64];    // [k][key], transposed K tile
    __shared__ float Vs[64][36];    // [key][d], pad 36 (bank spread)
    __shared__ float Ps[128][67];   // [row][key], pad 67 (1-phase scalar reads)

    int qb = blockIdx.x, h = blockIdx.y, b = blockIdx.z;
    int q0 = qb * 128;
    int tid = threadIdx.x;
    int ty = tid >> 3;        // 0..31
    int tx = tid & 7;         // 0..7

    const float* Qbase = g_Q + (((size_t)b * NHEAD + h) * NTOK + q0) * HDIM;
    const float* Kbase = g_K + ((size_t)b * NHEAD + h) * NTOK * HDIM;
    const float* Vbase = g_V + ((size_t)b * NHEAD + h) * NTOK * HDIM;
    const float* biasb = g_bias + ((size_t)h * NTOK + q0) * NTOK;
    const float* maskb = mask + ((size_t)(b & 7) * NTOK + q0) * NTOK;

    // stage Q transposed (once)
    {
        int r = tid & 127;
        int kb = (tid >> 7) * 16;
        const float* qp = Qbase + (size_t)r * HDIM + kb;
        #pragma unroll
        for (int u = 0; u < 16; u += 4) {
            float4 v = *(const float4*)(qp + u);
            Qt[kb + u + 0][r] = v.x;
            Qt[kb + u + 1][r] = v.y;
            Qt[kb + u + 2][r] = v.z;
            Qt[kb + u + 3][r] = v.w;
        }
    }

    float m_r[4], l_r[4], o[4][4];
    #pragma unroll
    for (int i = 0; i < 4; i++) {
        m_r[i] = -1e30f; l_r[i] = 0.f;
        #pragma unroll
        for (int j = 0; j < 4; j++) o[i][j] = 0.f;
    }

    for (int kt = 0; kt < 8; kt++) {
        __syncthreads();   // protect Kt/Vs/Ps from previous tile's readers
        // load K transposed
        {
            int j = tid & 63, kb = (tid >> 6) * 8;
            const float* kp = Kbase + (size_t)(kt * 64 + j) * HDIM + kb;
            float4 a = *(const float4*)kp;
            float4 c = *(const float4*)(kp + 4);
            Kt[kb + 0][j] = a.x; Kt[kb + 1][j] = a.y;
            Kt[kb + 2][j] = a.z; Kt[kb + 3][j] = a.w;
            Kt[kb + 4][j] = c.x; Kt[kb + 5][j] = c.y;
            Kt[kb + 6][j] = c.z; Kt[kb + 7][j] = c.w;
        }
        // load V natural
        {
            int j = tid >> 2, cb = (tid & 3) * 8;
            const float* vp = Vbase + (size_t)(kt * 64 + j) * HDIM + cb;
            *(float4*)&Vs[j][cb]     = *(const float4*)vp;
            *(float4*)&Vs[j][cb + 4] = *(const float4*)(vp + 4);
        }
        __syncthreads();

        // ---- S = Q @ K^T  (4x8 per thread) ----
        float s[4][8];
        #pragma unroll
        for (int i = 0; i < 4; i++)
            #pragma unroll
            for (int j = 0; j < 8; j++) s[i][j] = 0.f;

        #pragma unroll 4
        for (int kk = 0; kk < 32; kk++) {
            float a0[4], bv[8];
            *(float4*)&a0[0] = *(const float4*)&Qt[kk][ty * 4];
            *(float4*)&bv[0] = *(const float4*)&Kt[kk][tx * 8];
            *(float4*)&bv[4] = *(const float4*)&Kt[kk][tx * 8 + 4];
            #pragma unroll
            for (int i = 0; i < 4; i++)
                #pragma unroll
                for (int j = 0; j < 8; j++)
                    s[i][j] = fmaf(a0[i], bv[j], s[i][j]);
        }

        // ---- bias + mask + online softmax (rows owned in regs) ----
        #pragma unroll
        for (int i = 0; i < 4; i++) {
            int row = ty * 4 + i;
            const float* bp = biasb + (size_t)row * NTOK + kt * 64 + tx * 8;
            const float* mp = maskb + (size_t)row * NTOK + kt * 64 + tx * 8;
            float4 b0 = *(const float4*)bp;
            float4 b1 = *(const float4*)(bp + 4);
            float4 mm0 = *(const float4*)mp;
            float4 mm1 = *(const float4*)(mp + 4);
            s[i][0] += b0.x + mm0.x;  s[i][1] += b0.y + mm0.y;
            s[i][2] += b0.z + mm0.z;  s[i][3] += b0.w + mm0.w;
            s[i][4] += b1.x + mm1.x;  s[i][5] += b1.y + mm1.y;
            s[i][6] += b1.z + mm1.z;  s[i][7] += b1.w + mm1.w;

            float lm = s[i][0];
            #pragma unroll
            for (int j = 1; j < 8; j++) lm = fmaxf(lm, s[i][j]);
            lm = fmaxf(lm, __shfl_xor_sync(0xffffffffu, lm, 1));
            lm = fmaxf(lm, __shfl_xor_sync(0xffffffffu, lm, 2));
            lm = fmaxf(lm, __shfl_xor_sync(0xffffffffu, lm, 4));

            float nm = fmaxf(m_r[i], lm);
            float cr = __expf(m_r[i] - nm);
            float ls = 0.f;
            #pragma unroll
            for (int j = 0; j < 8; j++) {
                float p = __expf(s[i][j] - nm);
                s[i][j] = p;
                ls += p;
            }
            ls += __shfl_xor_sync(0xffffffffu, ls, 1);
            ls += __shfl_xor_sync(0xffffffffu, ls, 2);
            ls += __shfl_xor_sync(0xffffffffu, ls, 4);

            l_r[i] = l_r[i] * cr + ls;
            m_r[i] = nm;
            #pragma unroll
            for (int j = 0; j < 4; j++) o[i][j] *= cr;

            #pragma unroll
            for (int j = 0; j < 8; j++) Ps[row][tx * 8 + j] = s[i][j];
        }
        __syncthreads();

        // ---- O += P @ V  (4x4 per thread, same rows) ----
        #pragma unroll 4
        for (int j = 0; j < 64; j++) {
            float4 vv = *(const float4*)&Vs[j][tx * 4];
            float p0 = Ps[ty * 4 + 0][j];
            float p1 = Ps[ty * 4 + 1][j];
            float p2 = Ps[ty * 4 + 2][j];
            float p3 = Ps[ty * 4 + 3][j];
            o[0][0] = fmaf(p0, vv.x, o[0][0]);
            o[0][1] = fmaf(p0, vv.y, o[0][1]);
            o[0][2] = fmaf(p0, vv.z, o[0][2]);
            o[0][3] = fmaf(p0, vv.w, o[0][3]);
            o[1][0] = fmaf(p1, vv.x, o[1][0]);
            o[1][1] = fmaf(p1, vv.y, o[1][1]);
            o[1][2] = fmaf(p1, vv.z, o[1][2]);
            o[1][3] = fmaf(p1, vv.w, o[1][3]);
            o[2][0] = fmaf(p2, vv.x, o[2][0]);
            o[2][1] = fmaf(p2, vv.y, o[2][1]);
            o[2][2] = fmaf(p2, vv.z, o[2][2]);
            o[2][3] = fmaf(p2, vv.w, o[2][3]);
            o[3][0] = fmaf(p3, vv.x, o[3][0]);
            o[3][1] = fmaf(p3, vv.y, o[3][1]);
            o[3][2] = fmaf(p3, vv.z, o[3][2]);
            o[3][3] = fmaf(p3, vv.w, o[3][3]);
        }
    }

    // write out (b, tok, h*32 + c)
    float* op = g_att + ((size_t)b * NTOK + q0) * CDIM + (size_t)h * HDIM;
    #pragma unroll
    for (int i = 0; i < 4; i++) {
        int row = ty * 4 + i;
        float inv = 1.f / l_r[i];
        float4 r4 = make_float4(o[i][0] * inv, o[i][1] * inv,
                                o[i][2] * inv, o[i][3] * inv);
        *(float4*)(op + (size_t)row * CDIM + tx * 4) = r4;
    }
}

// ---------------------------------------------------------------------------
// Host launch
// ---------------------------------------------------------------------------
extern "C" void kernel_launch(void* const* d_in, const int* in_sizes, int n_in,
                              void* d_out, int out_size)
{
    const float *x = nullptr, *mask = nullptr, *qkv_w = nullptr, *qkv_b = nullptr;
    const float *proj_w = nullptr, *proj_b = nullptr;
    const float *pos_proj_w = nullptr, *pos_proj_b = nullptr;
    const float *ln1_g = nullptr, *ln1_b = nullptr, *pos1_w = nullptr, *pos1_b = nullptr;
    const float *ln2_g = nullptr, *ln2_b = nullptr, *pos2_w = nullptr, *pos2_b = nullptr;
    const float *ln3_g = nullptr, *ln3_b = nullptr, *pos3_w = nullptr, *pos3_b = nullptr;

    int cnt24 = 0, cnt576 = 0;
    for (int i = 0; i < n_in; i++) {
        int sz = in_sizes[i];
        const float* p = (const float*)d_in[i];
        switch (sz) {
            case 12582912: x = p; break;
            case 2097152:  mask = p; break;
            case 442368:   qkv_w = p; break;
            case 1152:     qkv_b = p; break;
            case 147456:   proj_w = p; break;
            case 384:      proj_b = p; break;
            case 72:       pos_proj_w = p; break;
            case 288:      pos3_w = p; break;
            case 12:       pos3_b = p; break;
            case 576:
                if (cnt576 == 0) pos1_w = p; else pos2_w = p;
                cnt576++;
                break;
            case 24: {
                switch (cnt24) {
                    case 0: pos_proj_b = p; break;
                    case 1: ln1_g = p; break;
                    case 2: ln1_b = p; break;
                    case 3: pos1_b = p; break;
                    case 4: ln2_g = p; break;
                    case 5: ln2_b = p; break;
                    case 6: pos2_b = p; break;
                    case 7: ln3_g = p; break;
                    case 8: ln3_b = p; break;
                }
                cnt24++;
                break;
            }
            default: break; // H, W, D scalars
        }
    }

    // 1. pos MLP table
    pos_mlp_kernel<<<(LPOS + 127) / 128, 128>>>(
        pos_proj_w, pos_proj_b,
        ln1_g, ln1_b, pos1_w, pos1_b,
        ln2_g, ln2_b, pos2_w, pos2_b,
        ln3_g, ln3_b, pos3_w, pos3_b);

    // 2. expand to per-head bias table
    bias_fill_kernel<<<(NTOK * NTOK) / 256, 256>>>();

    // 3. QKV GEMM + scatter
    gemm_kernel<<<dim3(1152 / 64, (BWIN * NTOK) / 128), 256>>>(
        x, qkv_w, qkv_b, 1152, 0, nullptr);

    // 4. fused attention (register-blocked)
    attn_kernel<<<dim3(NTOK / 128, NHEAD, BWIN), 256>>>(mask);

    // 5. output projection
    gemm_kernel<<<dim3(CDIM / 64, (BWIN * NTOK) / 128), 256>>>(
        nullptr, proj_w, proj_b, CDIM, 1, (float*)d_out);

    (void)out_size;
}